// round 6
// baseline (speedup 1.0000x reference)
#include <cuda_runtime.h>

#define DIM_B 4096
#define DIM_M 128
#define DIM_C 128
#define DIM_Q 256
#define VGB   16        // batches per block in vgemm
#define QCH   32        // q-chunk rows of W staged per step

// ---- scratch (static device globals: no allocation allowed) ----
__device__ float g_W [DIM_Q * DIM_Q];     // combined weight (256 x 256)
__device__ float g_xsum[DIM_B * DIM_Q];   // masked row sums (4 MB)
__device__ float g_v  [DIM_B * DIM_Q];    // per-batch query vectors (4 MB)
__device__ int   g_base[DIM_B];           // exclusive prefix sum of lens
__device__ int   g_sh_len;                // 0 = int32 seq_lengths, 1 = int64

typedef unsigned long long ull;

__device__ __forceinline__ ull pack2(float lo, float hi) {
    ull r; asm("mov.b64 %0, {%1, %2};" : "=l"(r) : "f"(lo), "f"(hi)); return r;
}
__device__ __forceinline__ void unpack2(ull v, float& lo, float& hi) {
    asm("mov.b64 {%0, %1}, %2;" : "=f"(lo), "=f"(hi) : "l"(v));
}
__device__ __forceinline__ ull fma2(ull a, ull b, ull c) {
    ull d; asm("fma.rn.f32x2 %0, %1, %2, %3;" : "=l"(d) : "l"(a), "l"(b), "l"(c)); return d;
}

// ---- K0: dtype detect + exclusive prefix scan of seq_lengths ----
__global__ void scan_kernel(const int* __restrict__ seq) {
    int sh = (seq[1] == 0) ? 1 : 0;
    if (threadIdx.x == 0) g_sh_len = sh;

    __shared__ int cs[1024], cs2[1024];
    int t = threadIdx.x;              // 1024 threads, 4 lens each
    int l[4]; int sum = 0;
#pragma unroll
    for (int i = 0; i < 4; i++) {
        l[i] = seq[(size_t)(4 * t + i) << sh];
        sum += l[i];
    }
    cs[t] = sum;
    __syncthreads();
    int* src = cs; int* dst = cs2;
    for (int off = 1; off < 1024; off <<= 1) {
        int v = src[t];
        if (t >= off) v += src[t - off];
        dst[t] = v;
        __syncthreads();
        int* tmp = src; src = dst; dst = tmp;
    }
    int run = (t > 0) ? src[t - 1] : 0;   // exclusive chunk base
#pragma unroll
    for (int i = 0; i < 4; i++) {
        g_base[4 * t + i] = run;
        run += l[i];
    }
}

// ---- K0a: fused W = (Wk^T Wc^T) @ proj. Block q computes row W[q][:]. ----
__global__ void wcomb_kernel(const float* __restrict__ Wk, const float* __restrict__ Wc,
                             const float* __restrict__ proj) {
    __shared__ float t1[DIM_M];       // T1[q][m] for this q
    int q = blockIdx.x;               // 0..255
    int t = threadIdx.x;              // 0..127
    float s = 0.f;
#pragma unroll 4
    for (int c = 0; c < DIM_C; c++)
        s = fmaf(Wk[c * DIM_Q + q], Wc[t * DIM_C + c], s);
    t1[t] = s;
    __syncthreads();
    float s0 = 0.f, s1 = 0.f;
#pragma unroll 4
    for (int m = 0; m < DIM_M; m++) {
        float a = t1[m];
        s0 = fmaf(a, proj[m * DIM_Q + t], s0);
        s1 = fmaf(a, proj[m * DIM_Q + 128 + t], s1);
    }
    g_W[q * DIM_Q + t]       = s0;
    g_W[q * DIM_Q + 128 + t] = s1;
}

// ---- K1: xsum[b][q] = sum_{m < len[b]} xss[b][m][q]  (block per batch) ----
__global__ void xsum_kernel(const float* __restrict__ xss, const int* __restrict__ seq) {
    int b   = blockIdx.x;
    int len = seq[(size_t)b << g_sh_len];
    int t   = threadIdx.x;           // 256 threads
    int q4  = t & 63;                // float4 column
    int mg  = t >> 6;                // row group 0..3
    const float4* base = (const float4*)xss + (size_t)b * (DIM_M * DIM_Q / 4);
    float4 acc = make_float4(0.f, 0.f, 0.f, 0.f);
#pragma unroll 4
    for (int m = mg; m < len; m += 4) {
        float4 v = base[m * (DIM_Q / 4) + q4];
        acc.x += v.x; acc.y += v.y; acc.z += v.z; acc.w += v.w;
    }
    __shared__ float4 red[4][64];
    red[mg][q4] = acc;
    __syncthreads();
    if (t < 64) {
        float4 a = red[0][t], c = red[1][t], d = red[2][t], e = red[3][t];
        float4 s;
        s.x = (a.x + c.x) + (d.x + e.x);
        s.y = (a.y + c.y) + (d.y + e.y);
        s.z = (a.z + c.z) + (d.z + e.z);
        s.w = (a.w + c.w) + (d.w + e.w);
        ((float4*)(g_xsum + (size_t)b * DIM_Q))[t] = s;
    }
}

// ---- K2: v = xsum @ W. 256 blocks x 512 threads, VGB=16 batches/block.
// W staged in QCH-row smem chunks with register prefetch of the next chunk.
__global__ void __launch_bounds__(512) vgemm_kernel() {
    __shared__ float xsT[DIM_Q][20];       // [q][16 data + 4 pad] 20 KB, rows 16B-aligned
    __shared__ float Wst[QCH * DIM_Q];     // 32 KB

    int t  = threadIdx.x;                  // 0..511
    int bb = blockIdx.x * VGB;

    // stage xsum transposed: xsT[q][g] = xsum[bb+g][q]
    for (int idx = t; idx < VGB * DIM_Q; idx += 512) {
        int g = idx >> 8, q = idx & 255;
        xsT[q][g] = g_xsum[(size_t)(bb + g) * DIM_Q + q];
    }

    const float4* Wg = (const float4*)g_W;   // 16384 float4; 2048 per chunk
    float4 r0 = Wg[t], r1 = Wg[t + 512], r2 = Wg[t + 1024], r3 = Wg[t + 1536];

    int c = t & 255, h = t >> 8;             // column, batch-half
    unsigned xs_base = (unsigned)__cvta_generic_to_shared(&xsT[0][0]) + h * 32;

    ull acc0 = 0ull, acc1 = 0ull, acc2 = 0ull, acc3 = 0ull;

    for (int ch = 0; ch < DIM_Q / QCH; ch++) {
        if (ch) __syncthreads();           // previous compute done before overwrite
        ((float4*)Wst)[t]        = r0;
        ((float4*)Wst)[t + 512]  = r1;
        ((float4*)Wst)[t + 1024] = r2;
        ((float4*)Wst)[t + 1536] = r3;
        __syncthreads();
        if (ch < DIM_Q / QCH - 1) {        // prefetch next chunk (overlaps compute)
            const float4* Wn = Wg + (ch + 1) * 2048;
            r0 = Wn[t]; r1 = Wn[t + 512]; r2 = Wn[t + 1024]; r3 = Wn[t + 1536];
        }
        unsigned xaddr = xs_base + (unsigned)(ch * QCH) * 80u;
#pragma unroll
        for (int kk = 0; kk < QCH; kk++) {
            float w = Wst[kk * DIM_Q + c];
            ull wp = pack2(w, w);
            ull a0, a1, a2, a3;
            asm volatile("ld.shared.v2.u64 {%0,%1}, [%2];"
                         : "=l"(a0), "=l"(a1) : "r"(xaddr));
            asm volatile("ld.shared.v2.u64 {%0,%1}, [%2+16];"
                         : "=l"(a2), "=l"(a3) : "r"(xaddr));
            acc0 = fma2(a0, wp, acc0);
            acc1 = fma2(a1, wp, acc1);
            acc2 = fma2(a2, wp, acc2);
            acc3 = fma2(a3, wp, acc3);
            xaddr += 80u;
        }
    }
    int b0 = bb + 8 * h;
    float lo, hi;
    unpack2(acc0, lo, hi);
    g_v[(size_t)(b0 + 0) * DIM_Q + c] = lo; g_v[(size_t)(b0 + 1) * DIM_Q + c] = hi;
    unpack2(acc1, lo, hi);
    g_v[(size_t)(b0 + 2) * DIM_Q + c] = lo; g_v[(size_t)(b0 + 3) * DIM_Q + c] = hi;
    unpack2(acc2, lo, hi);
    g_v[(size_t)(b0 + 4) * DIM_Q + c] = lo; g_v[(size_t)(b0 + 5) * DIM_Q + c] = hi;
    unpack2(acc3, lo, hi);
    g_v[(size_t)(b0 + 6) * DIM_Q + c] = lo; g_v[(size_t)(b0 + 7) * DIM_Q + c] = hi;
}

// ---- K3: y, block-per-batch, reversed order, 4-row ILP (8 LDG.128 in flight) ----
__global__ void y_kernel(const float* __restrict__ xss, const int* __restrict__ seq,
                         float* __restrict__ out) {
    int b    = (DIM_B - 1) - blockIdx.x;
    int len  = seq[(size_t)b << g_sh_len];
    int base = g_base[b];
    int t    = threadIdx.x;          // 256
    int w    = t >> 5, lane = t & 31;

    const float4* vr = (const float4*)(g_v + (size_t)b * DIM_Q);
    float4 v0 = vr[lane];
    float4 v1 = vr[lane + 32];

    const float4* xb = (const float4*)(xss + (size_t)b * DIM_M * DIM_Q);

    int m = w;
    for (; m + 24 < len; m += 32) {
        float4 a0 = xb[(size_t)m * 64 + lane];
        float4 a1 = xb[(size_t)m * 64 + 32 + lane];
        float4 b0 = xb[(size_t)(m + 8) * 64 + lane];
        float4 b1 = xb[(size_t)(m + 8) * 64 + 32 + lane];
        float4 c0 = xb[(size_t)(m + 16) * 64 + lane];
        float4 c1 = xb[(size_t)(m + 16) * 64 + 32 + lane];
        float4 d0 = xb[(size_t)(m + 24) * 64 + lane];
        float4 d1 = xb[(size_t)(m + 24) * 64 + 32 + lane];
        float s0 = 0.f, s1 = 0.f, s2 = 0.f, s3 = 0.f;
        s0 = fmaf(a0.x, v0.x, s0); s0 = fmaf(a0.y, v0.y, s0);
        s0 = fmaf(a0.z, v0.z, s0); s0 = fmaf(a0.w, v0.w, s0);
        s0 = fmaf(a1.x, v1.x, s0); s0 = fmaf(a1.y, v1.y, s0);
        s0 = fmaf(a1.z, v1.z, s0); s0 = fmaf(a1.w, v1.w, s0);
        s1 = fmaf(b0.x, v0.x, s1); s1 = fmaf(b0.y, v0.y, s1);
        s1 = fmaf(b0.z, v0.z, s1); s1 = fmaf(b0.w, v0.w, s1);
        s1 = fmaf(b1.x, v1.x, s1); s1 = fmaf(b1.y, v1.y, s1);
        s1 = fmaf(b1.z, v1.z, s1); s1 = fmaf(b1.w, v1.w, s1);
        s2 = fmaf(c0.x, v0.x, s2); s2 = fmaf(c0.y, v0.y, s2);
        s2 = fmaf(c0.z, v0.z, s2); s2 = fmaf(c0.w, v0.w, s2);
        s2 = fmaf(c1.x, v1.x, s2); s2 = fmaf(c1.y, v1.y, s2);
        s2 = fmaf(c1.z, v1.z, s2); s2 = fmaf(c1.w, v1.w, s2);
        s3 = fmaf(d0.x, v0.x, s3); s3 = fmaf(d0.y, v0.y, s3);
        s3 = fmaf(d0.z, v0.z, s3); s3 = fmaf(d0.w, v0.w, s3);
        s3 = fmaf(d1.x, v1.x, s3); s3 = fmaf(d1.y, v1.y, s3);
        s3 = fmaf(d1.z, v1.z, s3); s3 = fmaf(d1.w, v1.w, s3);
#pragma unroll
        for (int off = 16; off > 0; off >>= 1) {
            s0 += __shfl_xor_sync(0xffffffffu, s0, off);
            s1 += __shfl_xor_sync(0xffffffffu, s1, off);
            s2 += __shfl_xor_sync(0xffffffffu, s2, off);
            s3 += __shfl_xor_sync(0xffffffffu, s3, off);
        }
        if (lane == 0) {
            out[base + m]      = s0;
            out[base + m + 8]  = s1;
            out[base + m + 16] = s2;
            out[base + m + 24] = s3;
        }
    }
    for (; m < len; m += 8) {
        float4 a0 = xb[(size_t)m * 64 + lane];
        float4 a1 = xb[(size_t)m * 64 + 32 + lane];
        float s0 = 0.f;
        s0 = fmaf(a0.x, v0.x, s0); s0 = fmaf(a0.y, v0.y, s0);
        s0 = fmaf(a0.z, v0.z, s0); s0 = fmaf(a0.w, v0.w, s0);
        s0 = fmaf(a1.x, v1.x, s0); s0 = fmaf(a1.y, v1.y, s0);
        s0 = fmaf(a1.z, v1.z, s0); s0 = fmaf(a1.w, v1.w, s0);
#pragma unroll
        for (int off = 16; off > 0; off >>= 1)
            s0 += __shfl_xor_sync(0xffffffffu, s0, off);
        if (lane == 0) out[base + m] = s0;
    }
}

extern "C" void kernel_launch(void* const* d_in, const int* in_sizes, int n_in,
                              void* d_out, int out_size) {
    const float* xss  = (const float*)d_in[0];
    const float* Wk   = (const float*)d_in[1];
    const float* Wc   = (const float*)d_in[2];
    const float* proj = (const float*)d_in[3];
    const int*   seq  = (const int*)d_in[4];
    float* out = (float*)d_out;

    scan_kernel<<<1, 1024>>>(seq);
    wcomb_kernel<<<DIM_Q, DIM_C>>>(Wk, Wc, proj);
    xsum_kernel<<<DIM_B, 256>>>(xss, seq);
    vgemm_kernel<<<DIM_B / VGB, 512>>>();
    y_kernel<<<DIM_B, 256>>>(xss, seq, out);
}